// round 1
// baseline (speedup 1.0000x reference)
#include <cuda_runtime.h>
#include <cuda_bf16.h>
#include <math.h>

// Problem constants
#define SEQ    2048
#define DMODEL 1024
#define NH     4
#define DHEAD  256
#define NCHUNK 64
#define CSZ    32

// ---------------- scratch (device globals; allocation-free) ----------------
__device__ __align__(16) float g_qlin[SEQ * DMODEL];
__device__ __align__(16) float g_klin[SEQ * DMODEL];
__device__ __align__(16) float g_vlin[SEQ * DMODEL];
__device__ __align__(16) float g_q[SEQ * DMODEL];     // post conv+silu, then l2norm in place
__device__ __align__(16) float g_k[SEQ * DMODEL];
__device__ __align__(16) float g_v[SEQ * DMODEL];
__device__ __align__(16) float g_u[SEQ * DMODEL];     // T @ (v*beta)
__device__ __align__(16) float g_w[SEQ * DMODEL];     // T @ (k*beta)
__device__ __align__(16) float g_delta[SEQ * DMODEL];
__device__ __align__(16) float g_mix[SEQ * DMODEL];
__device__ __align__(16) float g_beta[SEQ * NH];
__device__ __align__(16) float g_probs[SEQ * NH * 5];
__device__ __align__(16) float g_attn[NH * NCHUNK * CSZ * CSZ];

// ---------------- SGEMM: C[M,N] = A[M,K] * B[N,K]^T (both row-major) -------
#define BM 128
#define BN 64
#define BK 16
__global__ __launch_bounds__(256) void sgemm_nt(const float* __restrict__ A,
                                                const float* __restrict__ B,
                                                float* __restrict__ C,
                                                int M, int N, int K) {
    __shared__ float As[BM][BK + 1];
    __shared__ float Bs[BN][BK + 1];
    int tid = threadIdx.x;
    int tx = tid & 15;   // N dir, 16 cols of 4
    int ty = tid >> 4;   // M dir, 16 rows of 8
    int bm = blockIdx.y * BM;
    int bn = blockIdx.x * BN;

    float acc[8][4];
#pragma unroll
    for (int i = 0; i < 8; i++)
#pragma unroll
        for (int j = 0; j < 4; j++) acc[i][j] = 0.f;

    for (int k0 = 0; k0 < K; k0 += BK) {
        // load A tile: 128x16 = 512 float4, 2 per thread
#pragma unroll
        for (int it = 0; it < 2; it++) {
            int l = tid + it * 256;
            int row = l >> 2;
            int c4 = (l & 3) * 4;
            float4 va = *(const float4*)(A + (size_t)(bm + row) * K + k0 + c4);
            As[row][c4 + 0] = va.x; As[row][c4 + 1] = va.y;
            As[row][c4 + 2] = va.z; As[row][c4 + 3] = va.w;
        }
        // load B tile: 64x16 = 256 float4, 1 per thread
        {
            int row = tid >> 2;
            int c4 = (tid & 3) * 4;
            float4 vb = *(const float4*)(B + (size_t)(bn + row) * K + k0 + c4);
            Bs[row][c4 + 0] = vb.x; Bs[row][c4 + 1] = vb.y;
            Bs[row][c4 + 2] = vb.z; Bs[row][c4 + 3] = vb.w;
        }
        __syncthreads();
#pragma unroll
        for (int kk = 0; kk < BK; kk++) {
            float ra[8], rb[4];
#pragma unroll
            for (int i = 0; i < 8; i++) ra[i] = As[ty * 8 + i][kk];
#pragma unroll
            for (int j = 0; j < 4; j++) rb[j] = Bs[tx * 4 + j][kk];
#pragma unroll
            for (int i = 0; i < 8; i++)
#pragma unroll
                for (int j = 0; j < 4; j++) acc[i][j] = fmaf(ra[i], rb[j], acc[i][j]);
        }
        __syncthreads();
    }
#pragma unroll
    for (int i = 0; i < 8; i++) {
        float4 o;
        o.x = acc[i][0]; o.y = acc[i][1]; o.z = acc[i][2]; o.w = acc[i][3];
        *(float4*)(C + (size_t)(bm + ty * 8 + i) * N + bn + tx * 4) = o;
    }
}

// ---------------- short conv (K=4, causal) + silu --------------------------
__global__ void conv_silu_kernel(const float* __restrict__ xin,
                                 const float* __restrict__ w,
                                 float* __restrict__ out) {
    int idx = blockIdx.x * blockDim.x + threadIdx.x;   // SEQ*DMODEL
    int c = idx & (DMODEL - 1);
    int t = idx >> 10;
    float acc = 0.f;
#pragma unroll
    for (int j = 0; j < 4; j++) {
        int tt = t + j - 3;
        if (tt >= 0) acc += xin[tt * DMODEL + c] * w[c * 4 + j];
    }
    out[idx] = acc / (1.f + expf(-acc));
}

// ---------------- beta (sigmoid) + gate probs ------------------------------
__global__ void beta_gate_kernel(const float* __restrict__ x,
                                 const float* __restrict__ Wb,
                                 const float* __restrict__ gate_w,
                                 const float* __restrict__ gate_b,
                                 const float* __restrict__ log_temp,
                                 const float* __restrict__ eps_param,
                                 float* __restrict__ beta_out,
                                 float* __restrict__ probs_out) {
    int t = blockIdx.x;
    __shared__ float sx[DMODEL];
    __shared__ float sdot[24];
    int tid = threadIdx.x;  // 256
    for (int i = tid; i < DMODEL; i += 256) sx[i] = x[t * DMODEL + i];
    __syncthreads();
    int warp = tid >> 5, lane = tid & 31;
    for (int o = warp; o < 24; o += 8) {
        const float* wrow = (o < 4) ? (Wb + o * DMODEL) : (gate_w + (o - 4) * DMODEL);
        float s = 0.f;
        for (int i = lane; i < DMODEL; i += 32) s += sx[i] * wrow[i];
#pragma unroll
        for (int off = 16; off; off >>= 1) s += __shfl_xor_sync(0xffffffffu, s, off);
        if (lane == 0) sdot[o] = s;
    }
    __syncthreads();
    if (tid < NH) {
        int h = tid;
        beta_out[t * NH + h] = 1.f / (1.f + expf(-sdot[h]));
        float temp = expf(log_temp[h]);
        float lg[5], mx = -1e30f;
#pragma unroll
        for (int p = 0; p < 5; p++) {
            lg[p] = (sdot[4 + h * 5 + p] + gate_b[h * 5 + p]) / temp;
            mx = fmaxf(mx, lg[p]);
        }
        float se = 0.f;
#pragma unroll
        for (int p = 0; p < 5; p++) { lg[p] = expf(lg[p] - mx); se += lg[p]; }
        float eps = fminf(fmaxf(eps_param[h], 0.f), 0.2f);
#pragma unroll
        for (int p = 0; p < 5; p++)
            probs_out[(t * NH + h) * 5 + p] = lg[p] / se * (1.f - 5.f * eps) + eps;
    }
}

// ---------------- l2 norm of q,k over head dim (in place) ------------------
__global__ void l2norm_qk_kernel(float* __restrict__ q, float* __restrict__ k) {
    int row = blockIdx.x;          // t*NH + h
    int t = row >> 2, h = row & 3;
    int base = t * DMODEL + h * DHEAD;
    int d = threadIdx.x;           // 256
    float qv = q[base + d], kv = k[base + d];
    float sq = qv * qv, sk = kv * kv;
#pragma unroll
    for (int off = 16; off; off >>= 1) {
        sq += __shfl_xor_sync(0xffffffffu, sq, off);
        sk += __shfl_xor_sync(0xffffffffu, sk, off);
    }
    __shared__ float red[2][8];
    int warp = d >> 5, lane = d & 31;
    if (lane == 0) { red[0][warp] = sq; red[1][warp] = sk; }
    __syncthreads();
    float ssq = 0.f, ssk = 0.f;
#pragma unroll
    for (int i = 0; i < 8; i++) { ssq += red[0][i]; ssk += red[1][i]; }
    q[base + d] = qv * rsqrtf(ssq + 1e-6f);
    k[base + d] = kv * rsqrtf(ssk + 1e-6f);
}

// ---------------- per-chunk UT transform (parallel over chunks) ------------
// smem layout (floats): sk[32][257], sx[32][257], sA[32][33], sT[32][33], sbeta[32]
#define CP_SMEM_FLOATS (2 * 32 * 257 + 2 * 32 * 33 + 32)
__global__ __launch_bounds__(256) void chunk_prep_kernel(const float* __restrict__ q,
                                                         const float* __restrict__ k,
                                                         const float* __restrict__ v,
                                                         const float* __restrict__ beta,
                                                         float* __restrict__ gu,
                                                         float* __restrict__ gw,
                                                         float* __restrict__ gattn) {
    extern __shared__ float smem[];
    float (*sk)[257] = (float (*)[257])smem;
    float (*sx)[257] = (float (*)[257])(smem + 32 * 257);
    float (*sA)[33]  = (float (*)[33])(smem + 2 * 32 * 257);
    float (*sT)[33]  = (float (*)[33])(smem + 2 * 32 * 257 + 32 * 33);
    float* sbeta     = smem + 2 * 32 * 257 + 2 * 32 * 33;

    int hb = blockIdx.x;               // h*NCHUNK + chunk
    int h = hb >> 6, ch = hb & 63;
    int t0 = ch * CSZ;
    int tid = threadIdx.x;

    for (int i = tid; i < CSZ * DHEAD; i += 256) {
        int r = i >> 8, d = i & 255;
        sk[r][d] = k[(t0 + r) * DMODEL + h * DHEAD + d];
    }
    if (tid < CSZ) sbeta[tid] = beta[(t0 + tid) * NH + h];
    __syncthreads();

    // A[i][j] = -beta_i * (k_i . k_j) for j<i
    for (int p = tid; p < CSZ * CSZ; p += 256) {
        int i = p >> 5, j = p & 31;
        float a = 0.f;
        if (j < i) {
            float s = 0.f;
            for (int d = 0; d < DHEAD; d++) s += sk[i][d] * sk[j][d];
            a = -sbeta[i] * s;
        }
        sA[i][j] = a;
    }
    __syncthreads();

    // T = (I - A)^{-1}, unit lower; forward substitution per column (lane)
    if (tid < 32) {
        int col = tid;
        for (int i = 0; i < CSZ; i++) {
            float tv = (col == i) ? 1.f : 0.f;
            for (int j = 0; j < i; j++) tv += sA[i][j] * sT[j][col];
            sT[i][col] = tv;
            __syncwarp();
        }
    }
    __syncthreads();

    // u = T @ (v * beta)
    for (int i = tid; i < CSZ * DHEAD; i += 256) {
        int r = i >> 8, d = i & 255;
        sx[r][d] = v[(t0 + r) * DMODEL + h * DHEAD + d] * sbeta[r];
    }
    __syncthreads();
    {
        int d = tid;
        for (int i = 0; i < CSZ; i++) {
            float a = 0.f;
            for (int j = 0; j <= i; j++) a += sT[i][j] * sx[j][d];
            gu[(t0 + i) * DMODEL + h * DHEAD + d] = a;
        }
    }
    // w = T @ (k * beta)
    {
        int d = tid;
        for (int i = 0; i < CSZ; i++) {
            float a = 0.f;
            for (int j = 0; j <= i; j++) a += sT[i][j] * sbeta[j] * sk[j][d];
            gw[(t0 + i) * DMODEL + h * DHEAD + d] = a;
        }
    }
    __syncthreads();
    // attn = tril(q k^T) (incl diagonal)
    for (int i = tid; i < CSZ * DHEAD; i += 256) {
        int r = i >> 8, d = i & 255;
        sx[r][d] = q[(t0 + r) * DMODEL + h * DHEAD + d];
    }
    __syncthreads();
    for (int p = tid; p < CSZ * CSZ; p += 256) {
        int i = p >> 5, j = p & 31;
        float a = 0.f;
        if (j <= i) {
            float s = 0.f;
            for (int d = 0; d < DHEAD; d++) s += sx[i][d] * sk[j][d];
            a = s;
        }
        gattn[(hb * CSZ + i) * CSZ + j] = a;
    }
}

// ---------------- sequential chunk scan, parallel over (head, dv-slice) ----
// slice width 8 -> 32 slices/head -> 128 blocks
#define SCAN_SMEM_FLOATS (3 * 32 * 256 + 256 * 9 + 256 + 256 + 1024)
__global__ __launch_bounds__(256) void delta_scan_kernel(const float* __restrict__ q,
                                                         const float* __restrict__ k,
                                                         const float* __restrict__ w,
                                                         const float* __restrict__ u,
                                                         const float* __restrict__ attn,
                                                         float* __restrict__ dout) {
    extern __shared__ float smem[];
    float (*sq)[256]  = (float (*)[256])smem;
    float (*skk)[256] = (float (*)[256])(smem + 8192);
    float (*sw)[256]  = (float (*)[256])(smem + 16384);
    float (*S)[9]     = (float (*)[9])(smem + 24576);
    float* su   = smem + 24576 + 2304;   // 32x8
    float* sua  = su + 256;              // 32x8
    float* satt = sua + 256;             // 32x32

    int b = blockIdx.x;
    int h = b >> 5, sl = b & 31;
    int tid = threadIdx.x;
    int r = tid >> 3, c = tid & 7;
    int cbase = h * DHEAD + sl * 8;

    float Sreg[8];
#pragma unroll
    for (int i = 0; i < 8; i++) Sreg[i] = 0.f;

    for (int ch = 0; ch < NCHUNK; ch++) {
        int t0 = ch * CSZ;
#pragma unroll
        for (int i = 0; i < 8; i++) S[tid][i] = Sreg[i];
        for (int i = tid; i < CSZ * DHEAD; i += 256) {
            int rr = i >> 8, d = i & 255;
            int gidx = (t0 + rr) * DMODEL + h * DHEAD + d;
            sq[rr][d]  = q[gidx];
            skk[rr][d] = k[gidx];
            sw[rr][d]  = w[gidx];
        }
        su[tid] = u[(t0 + r) * DMODEL + cbase + c];
        for (int i = tid; i < CSZ * CSZ; i += 256)
            satt[i] = attn[(h * NCHUNK + ch) * CSZ * CSZ + i];
        __syncthreads();

        // u_adj = u - w@S ; o_partial = q@S   (both (32x8))
        float au = su[tid], ao = 0.f;
#pragma unroll 8
        for (int d = 0; d < DHEAD; d++) {
            float sval = S[d][c];
            au = fmaf(-sw[r][d], sval, au);
            ao = fmaf(sq[r][d], sval, ao);
        }
        sua[tid] = au;
        __syncthreads();
#pragma unroll
        for (int j = 0; j < CSZ; j++) ao = fmaf(satt[r * CSZ + j], sua[j * 8 + c], ao);
        dout[(t0 + r) * DMODEL + cbase + c] = ao;

        // S += k^T @ u_adj ; thread tid owns row dk=tid of S-slice
#pragma unroll 8
        for (int j = 0; j < CSZ; j++) {
            float kv = skk[j][tid];
#pragma unroll
            for (int cc = 0; cc < 8; cc++) Sreg[cc] = fmaf(kv, sua[j * 8 + cc], Sreg[cc]);
        }
        __syncthreads();
    }
}

// ---------------- FIR(3/15/63) + gated mix + per-head RMSNorm --------------
__global__ void combine_kernel(const float* __restrict__ v,
                               const float* __restrict__ delta,
                               const float* __restrict__ probs,
                               const float* __restrict__ fs,
                               const float* __restrict__ fm,
                               const float* __restrict__ fl,
                               const float* __restrict__ normw,
                               float* __restrict__ out) {
    int row = blockIdx.x;           // t*NH + h
    int t = row >> 2, h = row & 3;
    int d = threadIdx.x;            // 256
    int cidx = h * DHEAD + d;
    const float* pb = probs + (t * NH + h) * 5;
    float p0 = pb[0], p1 = pb[1], p2 = pb[2], p3 = pb[3], p4 = pb[4];

    float ll = 0.f;
    for (int kk = 0; kk < 63; kk++) {
        int tt = t + kk - 62;
        if (tt >= 0) ll = fmaf(v[tt * DMODEL + cidx], fl[cidx * 63 + kk], ll);
    }
    float lm = 0.f;
#pragma unroll
    for (int kk = 0; kk < 15; kk++) {
        int tt = t + kk - 14;
        if (tt >= 0) lm = fmaf(v[tt * DMODEL + cidx], fm[cidx * 15 + kk], lm);
    }
    float ls = 0.f;
#pragma unroll
    for (int kk = 0; kk < 3; kk++) {
        int tt = t + kk - 2;
        if (tt >= 0) ls = fmaf(v[tt * DMODEL + cidx], fs[cidx * 3 + kk], ls);
    }
    float vcur = v[t * DMODEL + cidx];
    float mix = p0 * ls + p1 * lm + p2 * ll + p3 * delta[t * DMODEL + cidx] + p4 * vcur;

    float s = mix * mix;
#pragma unroll
    for (int off = 16; off; off >>= 1) s += __shfl_xor_sync(0xffffffffu, s, off);
    __shared__ float red[8];
    int warp = d >> 5, lane = d & 31;
    if (lane == 0) red[warp] = s;
    __syncthreads();
    float ms = 0.f;
#pragma unroll
    for (int i = 0; i < 8; i++) ms += red[i];
    out[t * DMODEL + cidx] = mix * rsqrtf(ms * (1.f / 256.f) + 1e-5f) * normw[d];
}

// ---------------- launch ---------------------------------------------------
extern "C" void kernel_launch(void* const* d_in, const int* in_sizes, int n_in,
                              void* d_out, int out_size) {
    const float* x       = (const float*)d_in[0];
    const float* Wq      = (const float*)d_in[1];
    const float* Wk      = (const float*)d_in[2];
    const float* Wv      = (const float*)d_in[3];
    const float* Wb      = (const float*)d_in[4];
    const float* conv_q  = (const float*)d_in[5];
    const float* conv_k  = (const float*)d_in[6];
    const float* conv_v  = (const float*)d_in[7];
    const float* fir_s   = (const float*)d_in[8];
    const float* fir_m   = (const float*)d_in[9];
    const float* fir_l   = (const float*)d_in[10];
    const float* gate_w  = (const float*)d_in[11];
    const float* gate_b  = (const float*)d_in[12];
    const float* log_tmp = (const float*)d_in[13];
    const float* eps_p   = (const float*)d_in[14];
    const float* norm_w  = (const float*)d_in[15];
    const float* Wo      = (const float*)d_in[16];
    float* out = (float*)d_out;

    float *qlin, *klin, *vlin, *qb, *kb, *vb, *ub, *wb, *db, *mixb, *betab, *probsb, *attnb;
    cudaGetSymbolAddress((void**)&qlin,  g_qlin);
    cudaGetSymbolAddress((void**)&klin,  g_klin);
    cudaGetSymbolAddress((void**)&vlin,  g_vlin);
    cudaGetSymbolAddress((void**)&qb,    g_q);
    cudaGetSymbolAddress((void**)&kb,    g_k);
    cudaGetSymbolAddress((void**)&vb,    g_v);
    cudaGetSymbolAddress((void**)&ub,    g_u);
    cudaGetSymbolAddress((void**)&wb,    g_w);
    cudaGetSymbolAddress((void**)&db,    g_delta);
    cudaGetSymbolAddress((void**)&mixb,  g_mix);
    cudaGetSymbolAddress((void**)&betab, g_beta);
    cudaGetSymbolAddress((void**)&probsb, g_probs);
    cudaGetSymbolAddress((void**)&attnb, g_attn);

    cudaFuncSetAttribute(chunk_prep_kernel, cudaFuncAttributeMaxDynamicSharedMemorySize,
                         CP_SMEM_FLOATS * 4);
    cudaFuncSetAttribute(delta_scan_kernel, cudaFuncAttributeMaxDynamicSharedMemorySize,
                         SCAN_SMEM_FLOATS * 4);

    dim3 gg(DMODEL / BN, SEQ / BM);   // (16, 16)

    sgemm_nt<<<gg, 256>>>(x, Wq, qlin, SEQ, DMODEL, DMODEL);
    sgemm_nt<<<gg, 256>>>(x, Wk, klin, SEQ, DMODEL, DMODEL);
    sgemm_nt<<<gg, 256>>>(x, Wv, vlin, SEQ, DMODEL, DMODEL);

    int nelem = SEQ * DMODEL;
    conv_silu_kernel<<<nelem / 256, 256>>>(qlin, conv_q, qb);
    conv_silu_kernel<<<nelem / 256, 256>>>(klin, conv_k, kb);
    conv_silu_kernel<<<nelem / 256, 256>>>(vlin, conv_v, vb);

    beta_gate_kernel<<<SEQ, 256>>>(x, Wb, gate_w, gate_b, log_tmp, eps_p, betab, probsb);
    l2norm_qk_kernel<<<SEQ * NH, 256>>>(qb, kb);

    chunk_prep_kernel<<<NH * NCHUNK, 256, CP_SMEM_FLOATS * 4>>>(qb, kb, vb, betab,
                                                                ub, wb, attnb);
    delta_scan_kernel<<<NH * 32, 256, SCAN_SMEM_FLOATS * 4>>>(qb, kb, wb, ub, attnb, db);

    combine_kernel<<<SEQ * NH, 256>>>(vb, db, probsb, fir_s, fir_m, fir_l, norm_w, mixb);

    sgemm_nt<<<gg, 256>>>(mixb, Wo, out, SEQ, DMODEL, DMODEL);
}

// round 3
// speedup vs baseline: 1.2535x; 1.2535x over previous
#include <cuda_runtime.h>
#include <cuda_bf16.h>
#include <cstdint>
#include <math.h>

// Problem constants
#define SEQ    2048
#define DMODEL 1024
#define NH     4
#define DHEAD  256
#define NCHUNK 64
#define CSZ    32

// ---------------- scratch (device globals; allocation-free) ----------------
__device__ __align__(16) float g_qlin[SEQ * DMODEL];
__device__ __align__(16) float g_klin[SEQ * DMODEL];
__device__ __align__(16) float g_vlin[SEQ * DMODEL];
__device__ __align__(16) float g_q[SEQ * DMODEL];
__device__ __align__(16) float g_k[SEQ * DMODEL];
__device__ __align__(16) float g_v[SEQ * DMODEL];
__device__ __align__(16) float g_u[SEQ * DMODEL];
__device__ __align__(16) float g_w[SEQ * DMODEL];
__device__ __align__(16) float g_delta[SEQ * DMODEL];
__device__ __align__(16) float g_mix[SEQ * DMODEL];
__device__ __align__(16) float g_beta[SEQ * NH];
__device__ __align__(16) float g_probs[SEQ * NH * 5];
__device__ __align__(16) float g_attn[NH * NCHUNK * CSZ * CSZ];

__device__ __forceinline__ float to_tf32(float x) {
    unsigned u;
    asm("cvt.rna.tf32.f32 %0, %1;" : "=r"(u) : "f"(x));
    return __uint_as_float(u);
}

// ---------------- TF32 tensor-core GEMM: C[M,N] = A[M,K] * B[N,K]^T --------
// Block 256 thr (8 warps), tile 128x128x16, warp tile 64x32 (4x4 m16n8k8),
// double-buffered smem, one sync per K-iter.
#define TGK 16
#define SROW 20   // padded row stride (floats)
__global__ __launch_bounds__(256, 1) void tgemm_nt(const float* __restrict__ A,
                                                   const float* __restrict__ B,
                                                   float* __restrict__ C,
                                                   int M, int N, int K) {
    __shared__ float As[2][128 * SROW];
    __shared__ float Bs[2][128 * SROW];
    int tid = threadIdx.x;
    int warp = tid >> 5, lane = tid & 31;
    int wm = warp >> 2;          // 0..1 -> M offset 64*wm
    int wn = warp & 3;           // 0..3 -> N offset 32*wn
    int g = lane >> 2, t = lane & 3;
    int bm = blockIdx.y * 128, bn = blockIdx.x * 128;

    float acc[4][4][4];
#pragma unroll
    for (int mi = 0; mi < 4; mi++)
#pragma unroll
        for (int nj = 0; nj < 4; nj++)
#pragma unroll
            for (int r = 0; r < 4; r++) acc[mi][nj][r] = 0.f;

    float4 ra[2], rb[2];
    const int row_l0 = (tid) >> 2,        c4_l0 = ((tid) & 3) * 4;
    const int row_l1 = (tid + 256) >> 2,  c4_l1 = ((tid + 256) & 3) * 4;

#define LDG_TILE(k0)                                                              \
    do {                                                                          \
        ra[0] = *(const float4*)(A + (size_t)(bm + row_l0) * K + (k0) + c4_l0);   \
        ra[1] = *(const float4*)(A + (size_t)(bm + row_l1) * K + (k0) + c4_l1);   \
        rb[0] = *(const float4*)(B + (size_t)(bn + row_l0) * K + (k0) + c4_l0);   \
        rb[1] = *(const float4*)(B + (size_t)(bn + row_l1) * K + (k0) + c4_l1);   \
    } while (0)

#define STS_TILE(buf)                                                             \
    do {                                                                          \
        float* pa0 = &As[buf][row_l0 * SROW + c4_l0];                             \
        pa0[0] = to_tf32(ra[0].x); pa0[1] = to_tf32(ra[0].y);                     \
        pa0[2] = to_tf32(ra[0].z); pa0[3] = to_tf32(ra[0].w);                     \
        float* pa1 = &As[buf][row_l1 * SROW + c4_l1];                             \
        pa1[0] = to_tf32(ra[1].x); pa1[1] = to_tf32(ra[1].y);                     \
        pa1[2] = to_tf32(ra[1].z); pa1[3] = to_tf32(ra[1].w);                     \
        float* pb0 = &Bs[buf][row_l0 * SROW + c4_l0];                             \
        pb0[0] = to_tf32(rb[0].x); pb0[1] = to_tf32(rb[0].y);                     \
        pb0[2] = to_tf32(rb[0].z); pb0[3] = to_tf32(rb[0].w);                     \
        float* pb1 = &Bs[buf][row_l1 * SROW + c4_l1];                             \
        pb1[0] = to_tf32(rb[1].x); pb1[1] = to_tf32(rb[1].y);                     \
        pb1[2] = to_tf32(rb[1].z); pb1[3] = to_tf32(rb[1].w);                     \
    } while (0)

    LDG_TILE(0);
    STS_TILE(0);
    __syncthreads();

    int nkt = K / TGK;
    for (int kt = 0; kt < nkt; kt++) {
        int buf = kt & 1;
        if (kt + 1 < nkt) LDG_TILE((kt + 1) * TGK);

#pragma unroll
        for (int ks = 0; ks < 2; ks++) {
            int kb = ks * 8;
            unsigned af[4][4], bf[4][2];
#pragma unroll
            for (int mi = 0; mi < 4; mi++) {
                int row = wm * 64 + mi * 16 + g;
                af[mi][0] = __float_as_uint(As[buf][row * SROW + kb + t]);
                af[mi][1] = __float_as_uint(As[buf][(row + 8) * SROW + kb + t]);
                af[mi][2] = __float_as_uint(As[buf][row * SROW + kb + t + 4]);
                af[mi][3] = __float_as_uint(As[buf][(row + 8) * SROW + kb + t + 4]);
            }
#pragma unroll
            for (int nj = 0; nj < 4; nj++) {
                int n = wn * 32 + nj * 8 + g;
                bf[nj][0] = __float_as_uint(Bs[buf][n * SROW + kb + t]);
                bf[nj][1] = __float_as_uint(Bs[buf][n * SROW + kb + t + 4]);
            }
#pragma unroll
            for (int mi = 0; mi < 4; mi++)
#pragma unroll
                for (int nj = 0; nj < 4; nj++) {
                    asm volatile(
                        "mma.sync.aligned.m16n8k8.row.col.f32.tf32.tf32.f32 "
                        "{%0,%1,%2,%3}, {%4,%5,%6,%7}, {%8,%9}, {%0,%1,%2,%3};"
                        : "+f"(acc[mi][nj][0]), "+f"(acc[mi][nj][1]),
                          "+f"(acc[mi][nj][2]), "+f"(acc[mi][nj][3])
                        : "r"(af[mi][0]), "r"(af[mi][1]), "r"(af[mi][2]), "r"(af[mi][3]),
                          "r"(bf[nj][0]), "r"(bf[nj][1]));
                }
        }
        if (kt + 1 < nkt) {
            STS_TILE(buf ^ 1);
            __syncthreads();
        }
    }

#pragma unroll
    for (int mi = 0; mi < 4; mi++) {
        int row = bm + wm * 64 + mi * 16 + g;
#pragma unroll
        for (int nj = 0; nj < 4; nj++) {
            int col = bn + wn * 32 + nj * 8 + t * 2;
            float2 v0 = make_float2(acc[mi][nj][0], acc[mi][nj][1]);
            float2 v1 = make_float2(acc[mi][nj][2], acc[mi][nj][3]);
            *(float2*)(C + (size_t)row * N + col) = v0;
            *(float2*)(C + (size_t)(row + 8) * N + col) = v1;
        }
    }
#undef LDG_TILE
#undef STS_TILE
}

// ---------------- short conv (K=4, causal) + silu --------------------------
__global__ void conv_silu_kernel(const float* __restrict__ xin,
                                 const float* __restrict__ w,
                                 float* __restrict__ out) {
    int idx = blockIdx.x * blockDim.x + threadIdx.x;
    int c = idx & (DMODEL - 1);
    int t = idx >> 10;
    float acc = 0.f;
#pragma unroll
    for (int j = 0; j < 4; j++) {
        int tt = t + j - 3;
        if (tt >= 0) acc += xin[tt * DMODEL + c] * w[c * 4 + j];
    }
    out[idx] = acc / (1.f + expf(-acc));
}

// ---------------- beta (sigmoid) + gate probs ------------------------------
__global__ void beta_gate_kernel(const float* __restrict__ x,
                                 const float* __restrict__ Wb,
                                 const float* __restrict__ gate_w,
                                 const float* __restrict__ gate_b,
                                 const float* __restrict__ log_temp,
                                 const float* __restrict__ eps_param,
                                 float* __restrict__ beta_out,
                                 float* __restrict__ probs_out) {
    int t = blockIdx.x;
    __shared__ float sx[DMODEL];
    __shared__ float sdot[24];
    int tid = threadIdx.x;
    for (int i = tid; i < DMODEL; i += 256) sx[i] = x[t * DMODEL + i];
    __syncthreads();
    int warp = tid >> 5, lane = tid & 31;
    for (int o = warp; o < 24; o += 8) {
        const float* wrow = (o < 4) ? (Wb + o * DMODEL) : (gate_w + (o - 4) * DMODEL);
        float s = 0.f;
        for (int i = lane; i < DMODEL; i += 32) s += sx[i] * wrow[i];
#pragma unroll
        for (int off = 16; off; off >>= 1) s += __shfl_xor_sync(0xffffffffu, s, off);
        if (lane == 0) sdot[o] = s;
    }
    __syncthreads();
    if (tid < NH) {
        int h = tid;
        beta_out[t * NH + h] = 1.f / (1.f + expf(-sdot[h]));
        float temp = expf(log_temp[h]);
        float lg[5], mx = -1e30f;
#pragma unroll
        for (int p = 0; p < 5; p++) {
            lg[p] = (sdot[4 + h * 5 + p] + gate_b[h * 5 + p]) / temp;
            mx = fmaxf(mx, lg[p]);
        }
        float se = 0.f;
#pragma unroll
        for (int p = 0; p < 5; p++) { lg[p] = expf(lg[p] - mx); se += lg[p]; }
        float eps = fminf(fmaxf(eps_param[h], 0.f), 0.2f);
#pragma unroll
        for (int p = 0; p < 5; p++)
            probs_out[(t * NH + h) * 5 + p] = lg[p] / se * (1.f - 5.f * eps) + eps;
    }
}

// ---------------- l2 norm of q,k over head dim (in place) ------------------
__global__ void l2norm_qk_kernel(float* __restrict__ q, float* __restrict__ k) {
    int row = blockIdx.x;
    int t = row >> 2, h = row & 3;
    int base = t * DMODEL + h * DHEAD;
    int d = threadIdx.x;
    float qv = q[base + d], kv = k[base + d];
    float sq = qv * qv, sk = kv * kv;
#pragma unroll
    for (int off = 16; off; off >>= 1) {
        sq += __shfl_xor_sync(0xffffffffu, sq, off);
        sk += __shfl_xor_sync(0xffffffffu, sk, off);
    }
    __shared__ float red[2][8];
    int warp = d >> 5, lane = d & 31;
    if (lane == 0) { red[0][warp] = sq; red[1][warp] = sk; }
    __syncthreads();
    float ssq = 0.f, ssk = 0.f;
#pragma unroll
    for (int i = 0; i < 8; i++) { ssq += red[0][i]; ssk += red[1][i]; }
    q[base + d] = qv * rsqrtf(ssq + 1e-6f);
    k[base + d] = kv * rsqrtf(ssk + 1e-6f);
}

// ---------------- per-chunk UT transform (parallel over chunks) ------------
#define CP_SMEM_FLOATS (2 * 32 * 257 + 2 * 32 * 33 + 32)
__global__ __launch_bounds__(256) void chunk_prep_kernel(const float* __restrict__ q,
                                                         const float* __restrict__ k,
                                                         const float* __restrict__ v,
                                                         const float* __restrict__ beta,
                                                         float* __restrict__ gu,
                                                         float* __restrict__ gw,
                                                         float* __restrict__ gattn) {
    extern __shared__ float smem[];
    float (*sk)[257] = (float (*)[257])smem;
    float (*sx)[257] = (float (*)[257])(smem + 32 * 257);
    float (*sA)[33]  = (float (*)[33])(smem + 2 * 32 * 257);
    float (*sT)[33]  = (float (*)[33])(smem + 2 * 32 * 257 + 32 * 33);
    float* sbeta     = smem + 2 * 32 * 257 + 2 * 32 * 33;

    int hb = blockIdx.x;
    int h = hb >> 6, ch = hb & 63;
    int t0 = ch * CSZ;
    int tid = threadIdx.x;

    for (int i = tid; i < CSZ * DHEAD; i += 256) {
        int r = i >> 8, d = i & 255;
        sk[r][d] = k[(t0 + r) * DMODEL + h * DHEAD + d];
    }
    if (tid < CSZ) sbeta[tid] = beta[(t0 + tid) * NH + h];
    __syncthreads();

    for (int p = tid; p < CSZ * CSZ; p += 256) {
        int i = p >> 5, j = p & 31;
        float a = 0.f;
        if (j < i) {
            float s = 0.f;
            for (int d = 0; d < DHEAD; d++) s += sk[i][d] * sk[j][d];
            a = -sbeta[i] * s;
        }
        sA[i][j] = a;
    }
    __syncthreads();

    if (tid < 32) {
        int col = tid;
        for (int i = 0; i < CSZ; i++) {
            float tv = (col == i) ? 1.f : 0.f;
            for (int j = 0; j < i; j++) tv += sA[i][j] * sT[j][col];
            sT[i][col] = tv;
            __syncwarp();
        }
    }
    __syncthreads();

    for (int i = tid; i < CSZ * DHEAD; i += 256) {
        int r = i >> 8, d = i & 255;
        sx[r][d] = v[(t0 + r) * DMODEL + h * DHEAD + d] * sbeta[r];
    }
    __syncthreads();
    {
        int d = tid;
        for (int i = 0; i < CSZ; i++) {
            float a = 0.f;
            for (int j = 0; j <= i; j++) a += sT[i][j] * sx[j][d];
            gu[(t0 + i) * DMODEL + h * DHEAD + d] = a;
        }
    }
    {
        int d = tid;
        for (int i = 0; i < CSZ; i++) {
            float a = 0.f;
            for (int j = 0; j <= i; j++) a += sT[i][j] * sbeta[j] * sk[j][d];
            gw[(t0 + i) * DMODEL + h * DHEAD + d] = a;
        }
    }
    __syncthreads();
    for (int i = tid; i < CSZ * DHEAD; i += 256) {
        int r = i >> 8, d = i & 255;
        sx[r][d] = q[(t0 + r) * DMODEL + h * DHEAD + d];
    }
    __syncthreads();
    for (int p = tid; p < CSZ * CSZ; p += 256) {
        int i = p >> 5, j = p & 31;
        float a = 0.f;
        if (j <= i) {
            float s = 0.f;
            for (int d = 0; d < DHEAD; d++) s += sx[i][d] * sk[j][d];
            a = s;
        }
        gattn[(hb * CSZ + i) * CSZ + j] = a;
    }
}

// ---------------- sequential chunk scan, parallel over (head, dv-slice) ----
#define SCAN_SMEM_FLOATS (3 * 32 * 256 + 256 * 9 + 256 + 256 + 1024)
__global__ __launch_bounds__(256) void delta_scan_kernel(const float* __restrict__ q,
                                                         const float* __restrict__ k,
                                                         const float* __restrict__ w,
                                                         const float* __restrict__ u,
                                                         const float* __restrict__ attn,
                                                         float* __restrict__ dout) {
    extern __shared__ float smem[];
    float (*sq)[256]  = (float (*)[256])smem;
    float (*skk)[256] = (float (*)[256])(smem + 8192);
    float (*sw)[256]  = (float (*)[256])(smem + 16384);
    float (*S)[9]     = (float (*)[9])(smem + 24576);
    float* su   = smem + 24576 + 2304;
    float* sua  = su + 256;
    float* satt = sua + 256;

    int b = blockIdx.x;
    int h = b >> 5, sl = b & 31;
    int tid = threadIdx.x;
    int r = tid >> 3, c = tid & 7;
    int cbase = h * DHEAD + sl * 8;

    float Sreg[8];
#pragma unroll
    for (int i = 0; i < 8; i++) Sreg[i] = 0.f;

    for (int ch = 0; ch < NCHUNK; ch++) {
        int t0 = ch * CSZ;
#pragma unroll
        for (int i = 0; i < 8; i++) S[tid][i] = Sreg[i];
        for (int i = tid; i < CSZ * DHEAD; i += 256) {
            int rr = i >> 8, d = i & 255;
            int gidx = (t0 + rr) * DMODEL + h * DHEAD + d;
            sq[rr][d]  = q[gidx];
            skk[rr][d] = k[gidx];
            sw[rr][d]  = w[gidx];
        }
        su[tid] = u[(t0 + r) * DMODEL + cbase + c];
        for (int i = tid; i < CSZ * CSZ; i += 256)
            satt[i] = attn[(h * NCHUNK + ch) * CSZ * CSZ + i];
        __syncthreads();

        float au = su[tid], ao = 0.f;
#pragma unroll 8
        for (int d = 0; d < DHEAD; d++) {
            float sval = S[d][c];
            au = fmaf(-sw[r][d], sval, au);
            ao = fmaf(sq[r][d], sval, ao);
        }
        sua[tid] = au;
        __syncthreads();
#pragma unroll
        for (int j = 0; j < CSZ; j++) ao = fmaf(satt[r * CSZ + j], sua[j * 8 + c], ao);
        dout[(t0 + r) * DMODEL + cbase + c] = ao;

#pragma unroll 8
        for (int j = 0; j < CSZ; j++) {
            float kv = skk[j][tid];
#pragma unroll
            for (int cc = 0; cc < 8; cc++) Sreg[cc] = fmaf(kv, sua[j * 8 + cc], Sreg[cc]);
        }
        __syncthreads();
    }
}

// ---------------- FIR(3/15/63) + gated mix + per-head RMSNorm --------------
__global__ void combine_kernel(const float* __restrict__ v,
                               const float* __restrict__ delta,
                               const float* __restrict__ probs,
                               const float* __restrict__ fs,
                               const float* __restrict__ fm,
                               const float* __restrict__ fl,
                               const float* __restrict__ normw,
                               float* __restrict__ out) {
    int row = blockIdx.x;
    int t = row >> 2, h = row & 3;
    int d = threadIdx.x;
    int cidx = h * DHEAD + d;
    const float* pb = probs + (t * NH + h) * 5;
    float p0 = pb[0], p1 = pb[1], p2 = pb[2], p3 = pb[3], p4 = pb[4];

    float ll = 0.f;
    for (int kk = 0; kk < 63; kk++) {
        int tt = t + kk - 62;
        if (tt >= 0) ll = fmaf(v[tt * DMODEL + cidx], fl[cidx * 63 + kk], ll);
    }
    float lm = 0.f;
#pragma unroll
    for (int kk = 0; kk < 15; kk++) {
        int tt = t + kk - 14;
        if (tt >= 0) lm = fmaf(v[tt * DMODEL + cidx], fm[cidx * 15 + kk], lm);
    }
    float ls = 0.f;
#pragma unroll
    for (int kk = 0; kk < 3; kk++) {
        int tt = t + kk - 2;
        if (tt >= 0) ls = fmaf(v[tt * DMODEL + cidx], fs[cidx * 3 + kk], ls);
    }
    float vcur = v[t * DMODEL + cidx];
    float mix = p0 * ls + p1 * lm + p2 * ll + p3 * delta[t * DMODEL + cidx] + p4 * vcur;

    float s = mix * mix;
#pragma unroll
    for (int off = 16; off; off >>= 1) s += __shfl_xor_sync(0xffffffffu, s, off);
    __shared__ float red[8];
    int warp = d >> 5, lane = d & 31;
    if (lane == 0) red[warp] = s;
    __syncthreads();
    float ms = 0.f;
#pragma unroll
    for (int i = 0; i < 8; i++) ms += red[i];
    out[t * DMODEL + cidx] = mix * rsqrtf(ms * (1.f / 256.f) + 1e-5f) * normw[d];
}

// ---------------- launch ---------------------------------------------------
extern "C" void kernel_launch(void* const* d_in, const int* in_sizes, int n_in,
                              void* d_out, int out_size) {
    const float* x       = (const float*)d_in[0];
    const float* Wq      = (const float*)d_in[1];
    const float* Wk      = (const float*)d_in[2];
    const float* Wv      = (const float*)d_in[3];
    const float* Wb      = (const float*)d_in[4];
    const float* conv_q  = (const float*)d_in[5];
    const float* conv_k  = (const float*)d_in[6];
    const float* conv_v  = (const float*)d_in[7];
    const float* fir_s   = (const float*)d_in[8];
    const float* fir_m   = (const float*)d_in[9];
    const float* fir_l   = (const float*)d_in[10];
    const float* gate_w  = (const float*)d_in[11];
    const float* gate_b  = (const float*)d_in[12];
    const float* log_tmp = (const float*)d_in[13];
    const float* eps_p   = (const float*)d_in[14];
    const float* norm_w  = (const float*)d_in[15];
    const float* Wo      = (const float*)d_in[16];
    float* out = (float*)d_out;

    float *qlin, *klin, *vlin, *qb, *kb, *vb, *ub, *wb, *db, *mixb, *betab, *probsb, *attnb;
    cudaGetSymbolAddress((void**)&qlin,  g_qlin);
    cudaGetSymbolAddress((void**)&klin,  g_klin);
    cudaGetSymbolAddress((void**)&vlin,  g_vlin);
    cudaGetSymbolAddress((void**)&qb,    g_q);
    cudaGetSymbolAddress((void**)&kb,    g_k);
    cudaGetSymbolAddress((void**)&vb,    g_v);
    cudaGetSymbolAddress((void**)&ub,    g_u);
    cudaGetSymbolAddress((void**)&wb,    g_w);
    cudaGetSymbolAddress((void**)&db,    g_delta);
    cudaGetSymbolAddress((void**)&mixb,  g_mix);
    cudaGetSymbolAddress((void**)&betab, g_beta);
    cudaGetSymbolAddress((void**)&probsb, g_probs);
    cudaGetSymbolAddress((void**)&attnb, g_attn);

    cudaFuncSetAttribute(chunk_prep_kernel, cudaFuncAttributeMaxDynamicSharedMemorySize,
                         CP_SMEM_FLOATS * 4);
    cudaFuncSetAttribute(delta_scan_kernel, cudaFuncAttributeMaxDynamicSharedMemorySize,
                         SCAN_SMEM_FLOATS * 4);

    dim3 gg(DMODEL / 128, SEQ / 128);   // (8, 16)

    tgemm_nt<<<gg, 256>>>(x, Wq, qlin, SEQ, DMODEL, DMODEL);
    tgemm_nt<<<gg, 256>>>(x, Wk, klin, SEQ, DMODEL, DMODEL);
    tgemm_nt<<<gg, 256>>>(x, Wv, vlin, SEQ, DMODEL, DMODEL);

    int nelem = SEQ * DMODEL;
    conv_silu_kernel<<<nelem / 256, 256>>>(qlin, conv_q, qb);
    conv_silu_kernel<<<nelem / 256, 256>>>(klin, conv_k, kb);
    conv_silu_kernel<<<nelem / 256, 256>>>(vlin, conv_v, vb);

    beta_gate_kernel<<<SEQ, 256>>>(x, Wb, gate_w, gate_b, log_tmp, eps_p, betab, probsb);
    l2norm_qk_kernel<<<SEQ * NH, 256>>>(qb, kb);

    chunk_prep_kernel<<<NH * NCHUNK, 256, CP_SMEM_FLOATS * 4>>>(qb, kb, vb, betab,
                                                                ub, wb, attnb);
    delta_scan_kernel<<<NH * 32, 256, SCAN_SMEM_FLOATS * 4>>>(qb, kb, wb, ub, attnb, db);

    combine_kernel<<<SEQ * NH, 256>>>(vb, db, probsb, fir_s, fir_m, fir_l, norm_w, mixb);

    tgemm_nt<<<gg, 256>>>(mixb, Wo, out, SEQ, DMODEL, DMODEL);
}